// round 8
// baseline (speedup 1.0000x reference)
#include <cuda_runtime.h>
#include <cstdint>

// Problem capacities (from reference: N=100000, E=1600000, 128->128->64)
#define MAXN 100000
#define MAXE 1600000

// ---------------- scratch (__device__ globals, 256B-aligned for vector ops) --
__device__ __align__(256) float g_deg[MAXN];
__device__ __align__(256) float g_dinv[MAXN];
__device__ __align__(256) int   g_cnt[MAXN];
__device__ __align__(256) int   g_cursor[MAXN];
__device__ __align__(256) int   g_off[MAXN + 2];
__device__ __align__(256) int   g_bsum[1024];
__device__ __align__(256) int   g_boff[1024];
__device__ __align__(256) int2  g_epack[MAXE];            // {src, bits(w*dinv[src])}
__device__ __align__(256) float g_h [(size_t)MAXN * 128]; // x @ W1
__device__ __align__(256) float g_h1[(size_t)MAXN * 128]; // relu(agg1 + b1)
__device__ __align__(256) float g_h2[(size_t)MAXN * 64];  // h1 @ W2

// ---------------- init: deg=1 (self loop), counters=0 -----------------------
__global__ void init_kernel(int n, int e) {
    int i = blockIdx.x * blockDim.x + threadIdx.x;
    if (i == 0) g_off[n] = e;
    if (i < n) {
        g_deg[i] = 1.0f;   // self-loop weight 1
        g_cnt[i] = 0;
        g_cursor[i] = 0;
    }
}

// ---------------- degree + histogram over destination (col) -----------------
// edge_index is int32 (JAX default x64-disabled downcasts jnp.int64 -> int32).
__global__ void hist_kernel(int e, const int* __restrict__ ei,
                            const float* __restrict__ ew) {
    int i = blockIdx.x * blockDim.x + threadIdx.x;
    if (i >= e) return;
    int c = ei[e + i];                         // col = ei[1][i]
    atomicAdd(&g_deg[c], ew[i]);
    atomicAdd(&g_cnt[c], 1);
}

__global__ void dinv_kernel(int n) {
    int i = blockIdx.x * blockDim.x + threadIdx.x;
    if (i < n) g_dinv[i] = rsqrtf(g_deg[i]);   // deg >= 1 always
}

// ---------------- 2-level exclusive scan of g_cnt -> g_off ------------------
__global__ void scan_partial(int n) {
    __shared__ int s[256];
    int t = threadIdx.x;
    int base = blockIdx.x * 1024;
    int sum = 0;
    for (int i = t; i < 1024; i += 256) {
        int idx = base + i;
        if (idx < n) sum += g_cnt[idx];
    }
    s[t] = sum;
    __syncthreads();
    for (int d = 128; d > 0; d >>= 1) {
        if (t < d) s[t] += s[t + d];
        __syncthreads();
    }
    if (t == 0) g_bsum[blockIdx.x] = s[0];
}

__global__ void scan_bsums(int nb) {
    __shared__ int s[1024];
    int t = threadIdx.x;
    int v = (t < nb) ? g_bsum[t] : 0;
    s[t] = v;
    for (int d = 1; d < 1024; d <<= 1) {
        __syncthreads();
        int add = (t >= d) ? s[t - d] : 0;
        __syncthreads();
        s[t] += add;
    }
    if (t < nb) g_boff[t] = s[t] - v;          // exclusive
}

__global__ void scan_final(int n) {
    __shared__ int s[1024];
    int t = threadIdx.x;
    int idx = blockIdx.x * 1024 + t;
    int v = (idx < n) ? g_cnt[idx] : 0;
    s[t] = v;
    for (int d = 1; d < 1024; d <<= 1) {
        __syncthreads();
        int add = (t >= d) ? s[t - d] : 0;
        __syncthreads();
        s[t] += add;
    }
    if (idx < n) g_off[idx] = g_boff[blockIdx.x] + s[t] - v;
}

// ---------------- scatter edges into CSR buckets -----------------------------
__global__ void scatter_kernel(int e, const int* __restrict__ ei,
                               const float* __restrict__ ew) {
    int i = blockIdx.x * blockDim.x + threadIdx.x;
    if (i >= e) return;
    int r = ei[i];
    int c = ei[e + i];
    int pos = g_off[c] + atomicAdd(&g_cursor[c], 1);
    float sw = ew[i] * g_dinv[r];              // w * d_src^{-1/2}
    g_epack[pos] = make_int2(r, __float_as_int(sw));
}

// ---------------- dense GEMM body: Y[n,OC] = X[n,K] @ W[K,OC] ----------------
// 256 threads/block. K chunked by KC=64 so static shared stays <= 40KB.
template <int K, int OC>
__device__ __forceinline__ void gemm_body(int n, const float* __restrict__ X,
                                          const float* __restrict__ W,
                                          float* __restrict__ Y) {
    constexpr int KC = 64;           // k-chunk
    constexpr int CG = OC / 4;       // float4 col groups
    constexpr int RG = 256 / CG;     // row groups
    constexpr int TR = RG * 4;       // tile rows per block
    __shared__ __align__(16) float Ws[KC * OC]; // 32KB (OC=128) / 16KB (OC=64)
    __shared__ __align__(16) float Xs[TR * KC]; // 8KB  (TR=32)  / 16KB (TR=64)

    int tid = threadIdx.x;
    int rbase = blockIdx.x * TR;
    int cg = tid % CG;
    int rg = tid / CG;

    float4 acc[4];
#pragma unroll
    for (int j = 0; j < 4; j++) acc[j] = make_float4(0.f, 0.f, 0.f, 0.f);

    for (int kc = 0; kc < K; kc += KC) {
        // stage W chunk [KC][OC]
        for (int i = tid; i < KC * OC / 4; i += 256)
            reinterpret_cast<float4*>(Ws)[i] =
                reinterpret_cast<const float4*>(W + (size_t)kc * OC)[i];
        // stage X chunk [TR][KC]
        for (int i = tid; i < TR * KC / 4; i += 256) {
            int rr = i / (KC / 4);
            int cc = i % (KC / 4);
            int row = rbase + rr;
            float4 v = make_float4(0.f, 0.f, 0.f, 0.f);
            if (row < n)
                v = reinterpret_cast<const float4*>(X + (size_t)row * K + kc)[cc];
            reinterpret_cast<float4*>(Xs)[i] = v;
        }
        __syncthreads();

#pragma unroll 4
        for (int k = 0; k < KC; k++) {
            float4 wv = reinterpret_cast<float4*>(Ws)[k * CG + cg];
#pragma unroll
            for (int j = 0; j < 4; j++) {
                float xv = Xs[(rg * 4 + j) * KC + k];
                acc[j].x = fmaf(xv, wv.x, acc[j].x);
                acc[j].y = fmaf(xv, wv.y, acc[j].y);
                acc[j].z = fmaf(xv, wv.z, acc[j].z);
                acc[j].w = fmaf(xv, wv.w, acc[j].w);
            }
        }
        __syncthreads();
    }

#pragma unroll
    for (int j = 0; j < 4; j++) {
        int row = rbase + rg * 4 + j;
        if (row < n)
            reinterpret_cast<float4*>(Y + (size_t)row * OC)[cg] = acc[j];
    }
}

__global__ __launch_bounds__(256) void gemm1_kernel(int n, const float* __restrict__ X,
                                                    const float* __restrict__ W) {
    gemm_body<128, 128>(n, X, W, g_h);
}

__global__ __launch_bounds__(256) void gemm2_kernel(int n, const float* __restrict__ W) {
    gemm_body<128, 64>(n, g_h1, W, g_h2);
}

// ---------------- aggregation: out[c] = d_c*(sum sw*h[src] + d_c*h[c]) + b --
// One warp per destination node; gather-only, no atomics.
template <int F, bool RELU>
__device__ __forceinline__ void agg_body(int n, const float* __restrict__ h,
                                         const float* __restrict__ bias,
                                         float* __restrict__ out) {
    int node = blockIdx.x * (blockDim.x >> 5) + (threadIdx.x >> 5);
    if (node >= n) return;
    int lane = threadIdx.x & 31;
    constexpr int V = F / 32;        // 4 (F=128) or 2 (F=64)
    float di = g_dinv[node];

    float acc[V];
    if constexpr (V == 4) {
        float4 hv = *reinterpret_cast<const float4*>(h + (size_t)node * F + lane * 4);
        acc[0] = di * hv.x; acc[1] = di * hv.y; acc[2] = di * hv.z; acc[3] = di * hv.w;
    } else {
        float2 hv = *reinterpret_cast<const float2*>(h + (size_t)node * F + lane * 2);
        acc[0] = di * hv.x; acc[1] = di * hv.y;
    }

    int e0 = g_off[node];
    int e1 = g_off[node + 1];
    int2 p = (e0 < e1) ? g_epack[e0] : make_int2(0, 0);
    for (int e = e0; e < e1; e++) {
        int2 cur = p;
        if (e + 1 < e1) p = g_epack[e + 1];   // prefetch next edge record
        int   r = cur.x;
        float w = __int_as_float(cur.y);
        if constexpr (V == 4) {
            float4 hv = *reinterpret_cast<const float4*>(h + (size_t)r * F + lane * 4);
            acc[0] = fmaf(w, hv.x, acc[0]);
            acc[1] = fmaf(w, hv.y, acc[1]);
            acc[2] = fmaf(w, hv.z, acc[2]);
            acc[3] = fmaf(w, hv.w, acc[3]);
        } else {
            float2 hv = *reinterpret_cast<const float2*>(h + (size_t)r * F + lane * 2);
            acc[0] = fmaf(w, hv.x, acc[0]);
            acc[1] = fmaf(w, hv.y, acc[1]);
        }
    }

#pragma unroll
    for (int v = 0; v < V; v++) {
        float o = fmaf(di, acc[v], bias[lane * V + v]);
        if (RELU) o = fmaxf(o, 0.f);
        out[(size_t)node * F + lane * V + v] = o;
    }
}

__global__ __launch_bounds__(256) void agg1_kernel(int n, const float* __restrict__ b1) {
    agg_body<128, true>(n, g_h, b1, g_h1);
}

__global__ __launch_bounds__(256) void agg2_kernel(int n, const float* __restrict__ b2,
                                                   float* __restrict__ out) {
    agg_body<64, false>(n, g_h2, b2, out);
}

// ---------------- launch (kernel launches ONLY) ------------------------------
extern "C" void kernel_launch(void* const* d_in, const int* in_sizes, int n_in,
                              void* d_out, int out_size) {
    const float* x  = (const float*)d_in[0];
    const int*   ei = (const int*)d_in[1];     // int32 edge_index (JAX x64 off)
    const float* ew = (const float*)d_in[2];
    const float* W1 = (const float*)d_in[3];
    const float* b1 = (const float*)d_in[4];
    const float* W2 = (const float*)d_in[5];
    const float* b2 = (const float*)d_in[6];
    float*       out = (float*)d_out;

    int n = in_sizes[0] / 128;
    int e = in_sizes[2];
    int nb = (n + 1023) / 1024;

    // --- graph preprocessing (deterministic per call) ---
    init_kernel<<<(n + 255) / 256, 256>>>(n, e);
    hist_kernel<<<(e + 255) / 256, 256>>>(e, ei, ew);
    dinv_kernel<<<(n + 255) / 256, 256>>>(n);
    scan_partial<<<nb, 256>>>(n);
    scan_bsums<<<1, 1024>>>(nb);
    scan_final<<<nb, 1024>>>(n);
    scatter_kernel<<<(e + 255) / 256, 256>>>(e, ei, ew);

    // --- layer 1: h = x@W1 ; h1 = relu(agg(h) + b1) ---
    gemm1_kernel<<<(n + 31) / 32, 256>>>(n, x, W1);
    agg1_kernel<<<(n + 7) / 8, 256>>>(n, b1);

    // --- layer 2: h2 = h1@W2 ; out = agg(h2) + b2 ---
    gemm2_kernel<<<(n + 63) / 64, 256>>>(n, W2);
    agg2_kernel<<<(n + 7) / 8, 256>>>(n, b2, out);
}

// round 9
// speedup vs baseline: 1.0035x; 1.0035x over previous
#include <cuda_runtime.h>
#include <cstdint>

// Problem capacities (from reference: N=100000, E=1600000, 128->128->64)
#define MAXN 100000
#define MAXE 1600000

// ---------------- scratch (__device__ globals, 256B-aligned for vector ops) --
__device__ __align__(256) float g_deg[MAXN];
__device__ __align__(256) float g_dinv[MAXN];
__device__ __align__(256) int   g_cnt[MAXN];
__device__ __align__(256) int   g_cursor[MAXN];
__device__ __align__(256) int   g_off[MAXN + 2];
__device__ __align__(256) int   g_bsum[1024];
__device__ __align__(256) int   g_boff[1024];
__device__ __align__(256) int2  g_epack[MAXE];            // {src, bits(w*dinv[src])}
__device__ __align__(256) float g_h [(size_t)MAXN * 128]; // x @ W1
__device__ __align__(256) float g_h1[(size_t)MAXN * 128]; // relu(agg1 + b1)
__device__ __align__(256) float g_h2[(size_t)MAXN * 64];  // h1 @ W2

// ---------------- init: deg=1 (self loop), counters=0 -----------------------
__global__ void init_kernel(int n, int e) {
    int i = blockIdx.x * blockDim.x + threadIdx.x;
    if (i == 0) g_off[n] = e;
    if (i < n) {
        g_deg[i] = 1.0f;   // self-loop weight 1
        g_cnt[i] = 0;
        g_cursor[i] = 0;
    }
}

// ---------------- degree + histogram over destination (col) -----------------
// edge_index is int32 (JAX default x64-disabled downcasts jnp.int64 -> int32).
__global__ void hist_kernel(int e, const int* __restrict__ ei,
                            const float* __restrict__ ew) {
    int i = blockIdx.x * blockDim.x + threadIdx.x;
    if (i >= e) return;
    int c = ei[e + i];                         // col = ei[1][i]
    atomicAdd(&g_deg[c], ew[i]);
    atomicAdd(&g_cnt[c], 1);
}

__global__ void dinv_kernel(int n) {
    int i = blockIdx.x * blockDim.x + threadIdx.x;
    if (i < n) g_dinv[i] = rsqrtf(g_deg[i]);   // deg >= 1 always
}

// ---------------- 2-level exclusive scan of g_cnt -> g_off ------------------
__global__ void scan_partial(int n) {
    __shared__ int s[256];
    int t = threadIdx.x;
    int base = blockIdx.x * 1024;
    int sum = 0;
    for (int i = t; i < 1024; i += 256) {
        int idx = base + i;
        if (idx < n) sum += g_cnt[idx];
    }
    s[t] = sum;
    __syncthreads();
    for (int d = 128; d > 0; d >>= 1) {
        if (t < d) s[t] += s[t + d];
        __syncthreads();
    }
    if (t == 0) g_bsum[blockIdx.x] = s[0];
}

__global__ void scan_bsums(int nb) {
    __shared__ int s[1024];
    int t = threadIdx.x;
    int v = (t < nb) ? g_bsum[t] : 0;
    s[t] = v;
    for (int d = 1; d < 1024; d <<= 1) {
        __syncthreads();
        int add = (t >= d) ? s[t - d] : 0;
        __syncthreads();
        s[t] += add;
    }
    if (t < nb) g_boff[t] = s[t] - v;          // exclusive
}

__global__ void scan_final(int n) {
    __shared__ int s[1024];
    int t = threadIdx.x;
    int idx = blockIdx.x * 1024 + t;
    int v = (idx < n) ? g_cnt[idx] : 0;
    s[t] = v;
    for (int d = 1; d < 1024; d <<= 1) {
        __syncthreads();
        int add = (t >= d) ? s[t - d] : 0;
        __syncthreads();
        s[t] += add;
    }
    if (idx < n) g_off[idx] = g_boff[blockIdx.x] + s[t] - v;
}

// ---------------- scatter edges into CSR buckets -----------------------------
__global__ void scatter_kernel(int e, const int* __restrict__ ei,
                               const float* __restrict__ ew) {
    int i = blockIdx.x * blockDim.x + threadIdx.x;
    if (i >= e) return;
    int r = ei[i];
    int c = ei[e + i];
    int pos = g_off[c] + atomicAdd(&g_cursor[c], 1);
    float sw = ew[i] * g_dinv[r];              // w * d_src^{-1/2}
    g_epack[pos] = make_int2(r, __float_as_int(sw));
}

// ---------------- dense GEMM body: Y[n,OC] = X[n,K] @ W[K,OC] ----------------
// 256 threads/block. K chunked by KC=64 so static shared stays <= 40KB.
template <int K, int OC>
__device__ __forceinline__ void gemm_body(int n, const float* __restrict__ X,
                                          const float* __restrict__ W,
                                          float* __restrict__ Y) {
    constexpr int KC = 64;           // k-chunk
    constexpr int CG = OC / 4;       // float4 col groups
    constexpr int RG = 256 / CG;     // row groups
    constexpr int TR = RG * 4;       // tile rows per block
    __shared__ __align__(16) float Ws[KC * OC]; // 32KB (OC=128) / 16KB (OC=64)
    __shared__ __align__(16) float Xs[TR * KC]; // 8KB  (TR=32)  / 16KB (TR=64)

    int tid = threadIdx.x;
    int rbase = blockIdx.x * TR;
    int cg = tid % CG;
    int rg = tid / CG;

    float4 acc[4];
#pragma unroll
    for (int j = 0; j < 4; j++) acc[j] = make_float4(0.f, 0.f, 0.f, 0.f);

    for (int kc = 0; kc < K; kc += KC) {
        // stage W chunk [KC][OC]
        for (int i = tid; i < KC * OC / 4; i += 256)
            reinterpret_cast<float4*>(Ws)[i] =
                reinterpret_cast<const float4*>(W + (size_t)kc * OC)[i];
        // stage X chunk [TR][KC]
        for (int i = tid; i < TR * KC / 4; i += 256) {
            int rr = i / (KC / 4);
            int cc = i % (KC / 4);
            int row = rbase + rr;
            float4 v = make_float4(0.f, 0.f, 0.f, 0.f);
            if (row < n)
                v = reinterpret_cast<const float4*>(X + (size_t)row * K + kc)[cc];
            reinterpret_cast<float4*>(Xs)[i] = v;
        }
        __syncthreads();

#pragma unroll 4
        for (int k = 0; k < KC; k++) {
            float4 wv = reinterpret_cast<float4*>(Ws)[k * CG + cg];
#pragma unroll
            for (int j = 0; j < 4; j++) {
                float xv = Xs[(rg * 4 + j) * KC + k];
                acc[j].x = fmaf(xv, wv.x, acc[j].x);
                acc[j].y = fmaf(xv, wv.y, acc[j].y);
                acc[j].z = fmaf(xv, wv.z, acc[j].z);
                acc[j].w = fmaf(xv, wv.w, acc[j].w);
            }
        }
        __syncthreads();
    }

#pragma unroll
    for (int j = 0; j < 4; j++) {
        int row = rbase + rg * 4 + j;
        if (row < n)
            reinterpret_cast<float4*>(Y + (size_t)row * OC)[cg] = acc[j];
    }
}

__global__ __launch_bounds__(256) void gemm1_kernel(int n, const float* __restrict__ X,
                                                    const float* __restrict__ W) {
    gemm_body<128, 128>(n, X, W, g_h);
}

__global__ __launch_bounds__(256) void gemm2_kernel(int n, const float* __restrict__ W) {
    gemm_body<128, 64>(n, g_h1, W, g_h2);
}

// ---------------- aggregation: out[c] = d_c*(sum sw*h[src] + d_c*h[c]) + b --
// One warp per destination node; gather-only, no atomics.
template <int F, bool RELU>
__device__ __forceinline__ void agg_body(int n, const float* __restrict__ h,
                                         const float* __restrict__ bias,
                                         float* __restrict__ out) {
    int node = blockIdx.x * (blockDim.x >> 5) + (threadIdx.x >> 5);
    if (node >= n) return;
    int lane = threadIdx.x & 31;
    constexpr int V = F / 32;        // 4 (F=128) or 2 (F=64)
    float di = g_dinv[node];

    float acc[V];
    if constexpr (V == 4) {
        float4 hv = *reinterpret_cast<const float4*>(h + (size_t)node * F + lane * 4);
        acc[0] = di * hv.x; acc[1] = di * hv.y; acc[2] = di * hv.z; acc[3] = di * hv.w;
    } else {
        float2 hv = *reinterpret_cast<const float2*>(h + (size_t)node * F + lane * 2);
        acc[0] = di * hv.x; acc[1] = di * hv.y;
    }

    int e0 = g_off[node];
    int e1 = g_off[node + 1];
    int2 p = (e0 < e1) ? g_epack[e0] : make_int2(0, 0);
    for (int e = e0; e < e1; e++) {
        int2 cur = p;
        if (e + 1 < e1) p = g_epack[e + 1];   // prefetch next edge record
        int   r = cur.x;
        float w = __int_as_float(cur.y);
        if constexpr (V == 4) {
            float4 hv = *reinterpret_cast<const float4*>(h + (size_t)r * F + lane * 4);
            acc[0] = fmaf(w, hv.x, acc[0]);
            acc[1] = fmaf(w, hv.y, acc[1]);
            acc[2] = fmaf(w, hv.z, acc[2]);
            acc[3] = fmaf(w, hv.w, acc[3]);
        } else {
            float2 hv = *reinterpret_cast<const float2*>(h + (size_t)r * F + lane * 2);
            acc[0] = fmaf(w, hv.x, acc[0]);
            acc[1] = fmaf(w, hv.y, acc[1]);
        }
    }

#pragma unroll
    for (int v = 0; v < V; v++) {
        float o = fmaf(di, acc[v], bias[lane * V + v]);
        if (RELU) o = fmaxf(o, 0.f);
        out[(size_t)node * F + lane * V + v] = o;
    }
}

__global__ __launch_bounds__(256) void agg1_kernel(int n, const float* __restrict__ b1) {
    agg_body<128, true>(n, g_h, b1, g_h1);
}

__global__ __launch_bounds__(256) void agg2_kernel(int n, const float* __restrict__ b2,
                                                   float* __restrict__ out) {
    agg_body<64, false>(n, g_h2, b2, out);
}

// ---------------- launch (kernel launches ONLY) ------------------------------
extern "C" void kernel_launch(void* const* d_in, const int* in_sizes, int n_in,
                              void* d_out, int out_size) {
    const float* x  = (const float*)d_in[0];
    const int*   ei = (const int*)d_in[1];     // int32 edge_index (JAX x64 off)
    const float* ew = (const float*)d_in[2];
    const float* W1 = (const float*)d_in[3];
    const float* b1 = (const float*)d_in[4];
    const float* W2 = (const float*)d_in[5];
    const float* b2 = (const float*)d_in[6];
    float*       out = (float*)d_out;

    int n = in_sizes[0] / 128;
    int e = in_sizes[2];
    int nb = (n + 1023) / 1024;

    // --- graph preprocessing (deterministic per call) ---
    init_kernel<<<(n + 255) / 256, 256>>>(n, e);
    hist_kernel<<<(e + 255) / 256, 256>>>(e, ei, ew);
    dinv_kernel<<<(n + 255) / 256, 256>>>(n);
    scan_partial<<<nb, 256>>>(n);
    scan_bsums<<<1, 1024>>>(nb);
    scan_final<<<nb, 1024>>>(n);
    scatter_kernel<<<(e + 255) / 256, 256>>>(e, ei, ew);

    // --- layer 1: h = x@W1 ; h1 = relu(agg(h) + b1) ---
    gemm1_kernel<<<(n + 31) / 32, 256>>>(n, x, W1);
    agg1_kernel<<<(n + 7) / 8, 256>>>(n, b1);

    // --- layer 2: h2 = h1@W2 ; out = agg(h2) + b2 ---
    gemm2_kernel<<<(n + 63) / 64, 256>>>(n, W2);
    agg2_kernel<<<(n + 7) / 8, 256>>>(n, b2, out);
}

// round 10
// speedup vs baseline: 1.1863x; 1.1822x over previous
#include <cuda_runtime.h>
#include <cstdint>

// Problem capacities (from reference: N=100000, E=1600000, 128->128->64)
#define MAXN 100000
#define MAXE 1600000

// ---------------- scratch (__device__ globals, 256B-aligned for vector ops) --
__device__ __align__(256) float g_deg[MAXN];
__device__ __align__(256) float g_dinv[MAXN];
__device__ __align__(256) int   g_cnt[MAXN];
__device__ __align__(256) int   g_cursor[MAXN];
__device__ __align__(256) int   g_off[MAXN + 2];
__device__ __align__(256) int   g_bsum[1024];
__device__ __align__(256) int   g_boff[1024];
__device__ __align__(256) int2  g_epack[MAXE];            // {src, bits(w*dinv[src])}
__device__ __align__(256) float g_h [(size_t)MAXN * 128]; // x @ W1
__device__ __align__(256) float g_h1[(size_t)MAXN * 128]; // relu(agg1 + b1)
__device__ __align__(256) float g_h2[(size_t)MAXN * 64];  // h1 @ W2

// ---------------- init: deg=1 (self loop), counters=0 -----------------------
__global__ void init_kernel(int n, int e) {
    int i = blockIdx.x * blockDim.x + threadIdx.x;
    if (i == 0) g_off[n] = e;
    if (i < n) {
        g_deg[i] = 1.0f;   // self-loop weight 1
        g_cnt[i] = 0;
        g_cursor[i] = 0;
    }
}

// ---------------- degree + histogram over destination (col) -----------------
// edge_index is int32 (JAX default x64-disabled downcasts jnp.int64 -> int32).
__global__ void hist_kernel(int e, const int* __restrict__ ei,
                            const float* __restrict__ ew) {
    int i = blockIdx.x * blockDim.x + threadIdx.x;
    if (i >= e) return;
    int c = ei[e + i];                         // col = ei[1][i]
    atomicAdd(&g_deg[c], ew[i]);
    atomicAdd(&g_cnt[c], 1);
}

__global__ void dinv_kernel(int n) {
    int i = blockIdx.x * blockDim.x + threadIdx.x;
    if (i < n) g_dinv[i] = rsqrtf(g_deg[i]);   // deg >= 1 always
}

// ---------------- 2-level exclusive scan of g_cnt -> g_off ------------------
__global__ void scan_partial(int n) {
    __shared__ int s[256];
    int t = threadIdx.x;
    int base = blockIdx.x * 1024;
    int sum = 0;
    for (int i = t; i < 1024; i += 256) {
        int idx = base + i;
        if (idx < n) sum += g_cnt[idx];
    }
    s[t] = sum;
    __syncthreads();
    for (int d = 128; d > 0; d >>= 1) {
        if (t < d) s[t] += s[t + d];
        __syncthreads();
    }
    if (t == 0) g_bsum[blockIdx.x] = s[0];
}

__global__ void scan_bsums(int nb) {
    __shared__ int s[1024];
    int t = threadIdx.x;
    int v = (t < nb) ? g_bsum[t] : 0;
    s[t] = v;
    for (int d = 1; d < 1024; d <<= 1) {
        __syncthreads();
        int add = (t >= d) ? s[t - d] : 0;
        __syncthreads();
        s[t] += add;
    }
    if (t < nb) g_boff[t] = s[t] - v;          // exclusive
}

__global__ void scan_final(int n) {
    __shared__ int s[1024];
    int t = threadIdx.x;
    int idx = blockIdx.x * 1024 + t;
    int v = (idx < n) ? g_cnt[idx] : 0;
    s[t] = v;
    for (int d = 1; d < 1024; d <<= 1) {
        __syncthreads();
        int add = (t >= d) ? s[t - d] : 0;
        __syncthreads();
        s[t] += add;
    }
    if (idx < n) g_off[idx] = g_boff[blockIdx.x] + s[t] - v;
}

// ---------------- scatter edges into CSR buckets -----------------------------
__global__ void scatter_kernel(int e, const int* __restrict__ ei,
                               const float* __restrict__ ew) {
    int i = blockIdx.x * blockDim.x + threadIdx.x;
    if (i >= e) return;
    int r = ei[i];
    int c = ei[e + i];
    int pos = g_off[c] + atomicAdd(&g_cursor[c], 1);
    float sw = ew[i] * g_dinv[r];              // w * d_src^{-1/2}
    g_epack[pos] = make_int2(r, __float_as_int(sw));
}

// ---------------- tf32 tensor-core GEMM: Y[n,OC] = X[n,128] @ W[128,OC] ------
__device__ __forceinline__ uint32_t f2tf(float x) {
    uint32_t r;
    asm("cvt.rna.tf32.f32 %0, %1;" : "=r"(r) : "f"(x));
    return r;
}

__device__ __forceinline__ void mma_tf32(float* c, const uint32_t* a,
                                         uint32_t b0, uint32_t b1) {
    asm volatile(
        "mma.sync.aligned.m16n8k8.row.col.f32.tf32.tf32.f32 "
        "{%0,%1,%2,%3}, {%4,%5,%6,%7}, {%8,%9}, {%0,%1,%2,%3};\n"
        : "+f"(c[0]), "+f"(c[1]), "+f"(c[2]), "+f"(c[3])
        : "r"(a[0]), "r"(a[1]), "r"(a[2]), "r"(a[3]), "r"(b0), "r"(b1));
}

// 128 threads (4 warps). Each warp: 32 rows x OC cols. K=128 in chunks of 32.
// A fragments loaded directly from gmem (X has no cross-block reuse);
// W chunk staged in smem as tf32 with row pad +4 (<=2-way LDS conflicts).
template <int OC>
__device__ __forceinline__ void gemm_tf32_body(int n, const float* __restrict__ X,
                                               const float* __restrict__ W,
                                               float* __restrict__ Y) {
    constexpr int K = 128;
    constexpr int KC = 32;           // k-chunk
    constexpr int OCP = OC + 4;      // padded smem row
    constexpr int NT = OC / 8;       // n-tiles of 8
    __shared__ __align__(16) uint32_t Ws[KC * OCP];

    int tid = threadIdx.x;
    int warp = tid >> 5;
    int lane = tid & 31;
    int g  = lane >> 2;              // 0..7
    int tg = lane & 3;               // 0..3
    int rbase = blockIdx.x * 128 + warp * 32;

    float acc[2][NT][4];
#pragma unroll
    for (int t = 0; t < 2; t++)
#pragma unroll
        for (int nt = 0; nt < NT; nt++)
#pragma unroll
            for (int j = 0; j < 4; j++) acc[t][nt][j] = 0.f;

    // clamped A rows (fully-OOB warps read row n-1; stores are guarded)
    int ra[2], rb[2];
#pragma unroll
    for (int t = 0; t < 2; t++) {
        ra[t] = min(rbase + t * 16 + g,     n - 1);
        rb[t] = min(rbase + t * 16 + g + 8, n - 1);
    }

    for (int kc = 0; kc < K; kc += KC) {
        // stage W chunk [KC][OC] -> tf32 smem
        for (int i = tid; i < KC * OC / 4; i += 128) {
            int kk = i / (OC / 4);
            int cc = i % (OC / 4);
            float4 v = reinterpret_cast<const float4*>(W + (size_t)(kc + kk) * OC)[cc];
            uint4 tv = make_uint4(f2tf(v.x), f2tf(v.y), f2tf(v.z), f2tf(v.w));
            *reinterpret_cast<uint4*>(&Ws[kk * OCP + cc * 4]) = tv;
        }
        __syncthreads();

#pragma unroll
        for (int ks = 0; ks < KC; ks += 8) {
            int k0 = kc + ks;
            uint32_t a[2][4];
#pragma unroll
            for (int t = 0; t < 2; t++) {
                a[t][0] = f2tf(X[(size_t)ra[t] * K + k0 + tg]);
                a[t][1] = f2tf(X[(size_t)rb[t] * K + k0 + tg]);
                a[t][2] = f2tf(X[(size_t)ra[t] * K + k0 + tg + 4]);
                a[t][3] = f2tf(X[(size_t)rb[t] * K + k0 + tg + 4]);
            }
#pragma unroll
            for (int nt = 0; nt < NT; nt++) {
                uint32_t b0 = Ws[(ks + tg)     * OCP + nt * 8 + g];
                uint32_t b1 = Ws[(ks + tg + 4) * OCP + nt * 8 + g];
                mma_tf32(acc[0][nt], a[0], b0, b1);
                mma_tf32(acc[1][nt], a[1], b0, b1);
            }
        }
        __syncthreads();
    }

    // store: c0,c1 at (row g, cols 2tg,2tg+1); c2,c3 at (row g+8)
#pragma unroll
    for (int t = 0; t < 2; t++) {
        int r0 = rbase + t * 16 + g;
        int r1 = r0 + 8;
#pragma unroll
        for (int nt = 0; nt < NT; nt++) {
            int col = nt * 8 + 2 * tg;
            if (r0 < n)
                *reinterpret_cast<float2*>(Y + (size_t)r0 * OC + col) =
                    make_float2(acc[t][nt][0], acc[t][nt][1]);
            if (r1 < n)
                *reinterpret_cast<float2*>(Y + (size_t)r1 * OC + col) =
                    make_float2(acc[t][nt][2], acc[t][nt][3]);
        }
    }
}

__global__ __launch_bounds__(128) void gemm1_kernel(int n, const float* __restrict__ X,
                                                    const float* __restrict__ W) {
    gemm_tf32_body<128>(n, X, W, g_h);
}

__global__ __launch_bounds__(128) void gemm2_kernel(int n, const float* __restrict__ W) {
    gemm_tf32_body<64>(n, g_h1, W, g_h2);
}

// ---------------- aggregation: out[c] = d_c*(sum sw*h[src] + d_c*h[c]) + b --
// One warp per destination node; gather-only, no atomics.
template <int F, bool RELU>
__device__ __forceinline__ void agg_body(int n, const float* __restrict__ h,
                                         const float* __restrict__ bias,
                                         float* __restrict__ out) {
    int node = blockIdx.x * (blockDim.x >> 5) + (threadIdx.x >> 5);
    if (node >= n) return;
    int lane = threadIdx.x & 31;
    constexpr int V = F / 32;        // 4 (F=128) or 2 (F=64)
    float di = g_dinv[node];

    float acc[V];
    if constexpr (V == 4) {
        float4 hv = *reinterpret_cast<const float4*>(h + (size_t)node * F + lane * 4);
        acc[0] = di * hv.x; acc[1] = di * hv.y; acc[2] = di * hv.z; acc[3] = di * hv.w;
    } else {
        float2 hv = *reinterpret_cast<const float2*>(h + (size_t)node * F + lane * 2);
        acc[0] = di * hv.x; acc[1] = di * hv.y;
    }

    int e0 = g_off[node];
    int e1 = g_off[node + 1];
    int2 p = (e0 < e1) ? g_epack[e0] : make_int2(0, 0);
    for (int e = e0; e < e1; e++) {
        int2 cur = p;
        if (e + 1 < e1) p = g_epack[e + 1];   // prefetch next edge record
        int   r = cur.x;
        float w = __int_as_float(cur.y);
        if constexpr (V == 4) {
            float4 hv = *reinterpret_cast<const float4*>(h + (size_t)r * F + lane * 4);
            acc[0] = fmaf(w, hv.x, acc[0]);
            acc[1] = fmaf(w, hv.y, acc[1]);
            acc[2] = fmaf(w, hv.z, acc[2]);
            acc[3] = fmaf(w, hv.w, acc[3]);
        } else {
            float2 hv = *reinterpret_cast<const float2*>(h + (size_t)r * F + lane * 2);
            acc[0] = fmaf(w, hv.x, acc[0]);
            acc[1] = fmaf(w, hv.y, acc[1]);
        }
    }

#pragma unroll
    for (int v = 0; v < V; v++) {
        float o = fmaf(di, acc[v], bias[lane * V + v]);
        if (RELU) o = fmaxf(o, 0.f);
        out[(size_t)node * F + lane * V + v] = o;
    }
}

__global__ __launch_bounds__(256) void agg1_kernel(int n, const float* __restrict__ b1) {
    agg_body<128, true>(n, g_h, b1, g_h1);
}

__global__ __launch_bounds__(256) void agg2_kernel(int n, const float* __restrict__ b2,
                                                   float* __restrict__ out) {
    agg_body<64, false>(n, g_h2, b2, out);
}

// ---------------- launch (kernel launches ONLY) ------------------------------
extern "C" void kernel_launch(void* const* d_in, const int* in_sizes, int n_in,
                              void* d_out, int out_size) {
    const float* x  = (const float*)d_in[0];
    const int*   ei = (const int*)d_in[1];     // int32 edge_index (JAX x64 off)
    const float* ew = (const float*)d_in[2];
    const float* W1 = (const float*)d_in[3];
    const float* b1 = (const float*)d_in[4];
    const float* W2 = (const float*)d_in[5];
    const float* b2 = (const float*)d_in[6];
    float*       out = (float*)d_out;

    int n = in_sizes[0] / 128;
    int e = in_sizes[2];
    int nb = (n + 1023) / 1024;

    // --- graph preprocessing (deterministic per call) ---
    init_kernel<<<(n + 255) / 256, 256>>>(n, e);
    hist_kernel<<<(e + 255) / 256, 256>>>(e, ei, ew);
    dinv_kernel<<<(n + 255) / 256, 256>>>(n);
    scan_partial<<<nb, 256>>>(n);
    scan_bsums<<<1, 1024>>>(nb);
    scan_final<<<nb, 1024>>>(n);
    scatter_kernel<<<(e + 255) / 256, 256>>>(e, ei, ew);

    // --- layer 1: h = x@W1 ; h1 = relu(agg(h) + b1) ---
    gemm1_kernel<<<(n + 127) / 128, 128>>>(n, x, W1);
    agg1_kernel<<<(n + 7) / 8, 256>>>(n, b1);

    // --- layer 2: h2 = h1@W2 ; out = agg(h2) + b2 ---
    gemm2_kernel<<<(n + 127) / 128, 128>>>(n, W2);
    agg2_kernel<<<(n + 7) / 8, 256>>>(n, b2, out);
}